// round 15
// baseline (speedup 1.0000x reference)
#include <cuda_runtime.h>
#include <cuda_bf16.h>
#include <stdint.h>

// Problem constants (fixed-shape problem; runtime sizes used for loop bounds)
#define NMAX 100000
#define EMAX 1600000
#define HDIM 128
#define FDIM 128
#define CDIM 64
#define GMAX 512

// ---------------- scratch (__device__ globals; no runtime allocation) ------
__device__ __nv_bfloat16 g_h1b[(size_t)NMAX * HDIM];  // 25.6 MB: dinv[v]*h1[v] rows (bf16)
__device__ float g_dinv[NMAX];
__device__ int   g_cnt[NMAX];                 // in-degree (edges only)
__device__ int   g_rowptr[NMAX];              // exclusive scan of g_cnt
__device__ int   g_pos[NMAX];                 // fill cursor (starts = rowptr)
__device__ int   g_csr[EMAX];                 // src ids grouped by dst
__device__ int   g_blocksums[256];
__device__ float g_readout[GMAX * HDIM];
__device__ float g_Wf[FDIM * HDIM];           // W_pre @ W_conv
__device__ float g_bf[HDIM];                  // b_pre @ W_conv
__device__ int   g_is64;

__device__ __forceinline__ int ld_idx(const void* p, long long i, bool w64) {
    return w64 ? (int)((const long long*)p)[i] : ((const int*)p)[i];
}

// ---------------- side stream for capture fork (static init, no dev alloc) --
static cudaStream_t s_side = nullptr;
static cudaEvent_t  s_ev1 = nullptr, s_ev2 = nullptr;
static bool s_fork_ok = false;
static struct SideInit {
    SideInit() {
        s_fork_ok =
            cudaStreamCreateWithFlags(&s_side, cudaStreamNonBlocking) == cudaSuccess &&
            cudaEventCreateWithFlags(&s_ev1, cudaEventDisableTiming) == cudaSuccess &&
            cudaEventCreateWithFlags(&s_ev2, cudaEventDisableTiming) == cudaSuccess;
    }
} s_side_init;

// ---------------- init: zero scratch + dtype detect + fuse W_pre@W_conv -----
__global__ void k_init(const int* __restrict__ ei_words,
                       const float* __restrict__ Wpre, const float* __restrict__ bpre,
                       const float* __restrict__ Wconv, int N, int G, int ZB) {
    if ((int)blockIdx.x < ZB) {
        int i = blockIdx.x * 256 + threadIdx.x;
        if (i == 0) {
            int acc = 0;
            for (int j = 1; j < 256; j += 2) acc |= ei_words[j];
            g_is64 = (acc == 0) ? 1 : 0;
        }
        int total = N + G * HDIM;
        if (i >= total) return;
        if (i < N) g_cnt[i] = 0;
        else       g_readout[i - N] = 0.f;
    } else {
        int bi = blockIdx.x - ZB;                   // 0..64
        int i = bi * 2 + (threadIdx.x >> 7);        // row 0..129
        int j = threadIdx.x & 127;
        if (i < FDIM) {
            float a = 0.f;
            #pragma unroll 8
            for (int k = 0; k < HDIM; k++) a += Wpre[i * HDIM + k] * Wconv[k * HDIM + j];
            g_Wf[i * HDIM + j] = a;
        } else if (i == FDIM) {
            float a = 0.f;
            #pragma unroll 8
            for (int k = 0; k < HDIM; k++) a += bpre[k] * Wconv[k * HDIM + j];
            g_bf[j] = a;
        }
    }
}

// ---------------- main GEMM: h1s = dinv*(x @ Wf + bf)  (tf32 mma, persistent)
#define XS_LD 132
#define WS_LD 136
#define GEMM_SMEM ((128 * WS_LD + 128 + 64 * XS_LD) * 4)
#define GEMM_GRID 296

__device__ __forceinline__ uint32_t f2tf32(float f) {
    uint32_t o;
    asm("cvt.rna.tf32.f32 %0, %1;" : "=r"(o) : "f"(f));
    return o;
}

__global__ __launch_bounds__(256) void k_gemm_mma(const float* __restrict__ x,
                                                  int N, int numTiles) {
    extern __shared__ float smf[];
    float* ws  = smf;                        // [128][WS_LD]
    float* bfs = smf + 128 * WS_LD;          // [128]
    float* xs  = smf + 128 * WS_LD + 128;    // [64][XS_LD]

    int tid  = threadIdx.x;
    int warp = tid >> 5, lane = tid & 31;
    int g4 = lane >> 2, t4 = lane & 3;
    int wm = warp >> 2, wn = warp & 3;

    #pragma unroll
    for (int i = 0; i < 16; i++) {
        int lin = tid + i * 256;
        int r = lin >> 5, c = (lin & 31) * 4;
        float4 v = *(const float4*)&g_Wf[r * HDIM + c];
        uint32_t* dst = (uint32_t*)&ws[r * WS_LD + c];
        dst[0] = f2tf32(v.x); dst[1] = f2tf32(v.y);
        dst[2] = f2tf32(v.z); dst[3] = f2tf32(v.w);
    }
    if (tid < HDIM) bfs[tid] = g_bf[tid];

    for (int tile = blockIdx.x; tile < numTiles; tile += gridDim.x) {
        int rb = tile * 64;
        __syncthreads();
        #pragma unroll
        for (int i = 0; i < 8; i++) {
            int lin = tid + i * 256;
            int r = lin >> 5, c = (lin & 31) * 4;
            int grow = rb + r;
            float4 v = (grow < N) ? *(const float4*)&x[(size_t)grow * FDIM + c]
                                  : make_float4(0.f, 0.f, 0.f, 0.f);
            uint32_t* dst = (uint32_t*)&xs[r * XS_LD + c];
            dst[0] = f2tf32(v.x); dst[1] = f2tf32(v.y);
            dst[2] = f2tf32(v.z); dst[3] = f2tf32(v.w);
        }
        __syncthreads();

        float acc[2][4][4];
        #pragma unroll
        for (int mt = 0; mt < 2; mt++)
            #pragma unroll
            for (int nt = 0; nt < 4; nt++)
                #pragma unroll
                for (int q = 0; q < 4; q++) acc[mt][nt][q] = 0.f;

        #pragma unroll
        for (int ks = 0; ks < 16; ks++) {
            int k0 = ks * 8;
            uint32_t a[2][4];
            #pragma unroll
            for (int mt = 0; mt < 2; mt++) {
                int r0 = wm * 32 + mt * 16;
                a[mt][0] = __float_as_uint(xs[(r0 + g4    ) * XS_LD + k0 + t4    ]);
                a[mt][1] = __float_as_uint(xs[(r0 + g4 + 8) * XS_LD + k0 + t4    ]);
                a[mt][2] = __float_as_uint(xs[(r0 + g4    ) * XS_LD + k0 + t4 + 4]);
                a[mt][3] = __float_as_uint(xs[(r0 + g4 + 8) * XS_LD + k0 + t4 + 4]);
            }
            #pragma unroll
            for (int nt = 0; nt < 4; nt++) {
                int nb = wn * 32 + nt * 8 + g4;
                uint32_t b0 = __float_as_uint(ws[(k0 + t4    ) * WS_LD + nb]);
                uint32_t b1 = __float_as_uint(ws[(k0 + t4 + 4) * WS_LD + nb]);
                #pragma unroll
                for (int mt = 0; mt < 2; mt++) {
                    asm volatile(
                        "mma.sync.aligned.m16n8k8.row.col.f32.tf32.tf32.f32 "
                        "{%0,%1,%2,%3}, {%4,%5,%6,%7}, {%8,%9}, {%0,%1,%2,%3};"
                        : "+f"(acc[mt][nt][0]), "+f"(acc[mt][nt][1]),
                          "+f"(acc[mt][nt][2]), "+f"(acc[mt][nt][3])
                        : "r"(a[mt][0]), "r"(a[mt][1]), "r"(a[mt][2]), "r"(a[mt][3]),
                          "r"(b0), "r"(b1));
                }
            }
        }

        // epilogue: (acc + bias) * dinv[row], convert to bf16, store
        #pragma unroll
        for (int mt = 0; mt < 2; mt++) {
            int r0 = rb + wm * 32 + mt * 16 + g4;
            float dv0 = (r0     < N) ? g_dinv[r0]     : 0.f;
            float dv1 = (r0 + 8 < N) ? g_dinv[r0 + 8] : 0.f;
            #pragma unroll
            for (int nt = 0; nt < 4; nt++) {
                int col = wn * 32 + nt * 8 + t4 * 2;
                float bv0 = bfs[col], bv1 = bfs[col + 1];
                if (r0 < N) {
                    __nv_bfloat162 o = __float22bfloat162_rn(
                        make_float2((acc[mt][nt][0] + bv0) * dv0,
                                    (acc[mt][nt][1] + bv1) * dv0));
                    *(__nv_bfloat162*)&g_h1b[(size_t)r0 * HDIM + col] = o;
                }
                if (r0 + 8 < N) {
                    __nv_bfloat162 o = __float22bfloat162_rn(
                        make_float2((acc[mt][nt][2] + bv0) * dv1,
                                    (acc[mt][nt][3] + bv1) * dv1));
                    *(__nv_bfloat162*)&g_h1b[(size_t)(r0 + 8) * HDIM + col] = o;
                }
            }
        }
    }
}

// ---------------- degree count (4 edges/thread, batched atomics) ------------
__global__ void k_count(const void* __restrict__ ei, int E) {
    bool w64 = g_is64 != 0;
    int i = (blockIdx.x * blockDim.x + threadIdx.x) * 4;
    if (i >= E) return;
    int n = min(4, E - i);
    int d[4];
    #pragma unroll
    for (int q = 0; q < 4; q++) if (q < n) d[q] = ld_idx(ei, (long long)E + i + q, w64);
    #pragma unroll
    for (int q = 0; q < 4; q++) if (q < n) atomicAdd(&g_cnt[d[q]], 1);
}

// ---------------- exclusive scan of g_cnt -> g_rowptr (+ dinv fused) -------
__global__ void k_scan1(int N) {
    __shared__ int sm[1024];
    int i = blockIdx.x * 1024 + threadIdx.x;
    int v = (i < N) ? g_cnt[i] : 0;
    if (i < N) g_dinv[i] = rsqrtf((float)(v + 1));
    sm[threadIdx.x] = v;
    __syncthreads();
    for (int off = 1; off < 1024; off <<= 1) {
        int t = (threadIdx.x >= off) ? sm[threadIdx.x - off] : 0;
        __syncthreads();
        sm[threadIdx.x] += t;
        __syncthreads();
    }
    if (i < N) g_rowptr[i] = sm[threadIdx.x] - v;
    if (threadIdx.x == 1023) g_blocksums[blockIdx.x] = sm[1023];
}

__global__ void k_scan2(int NB) {
    __shared__ int sm[256];
    int t = threadIdx.x;
    int v = (t < NB) ? g_blocksums[t] : 0;
    sm[t] = v;
    __syncthreads();
    for (int off = 1; off < 256; off <<= 1) {
        int u = (t >= off) ? sm[t - off] : 0;
        __syncthreads();
        sm[t] += u;
        __syncthreads();
    }
    if (t < NB) g_blocksums[t] = sm[t] - v;
}

__global__ void k_scan3(int N) {
    int i = blockIdx.x * 1024 + threadIdx.x;
    if (i < N) {
        int r = g_rowptr[i] + g_blocksums[blockIdx.x];
        g_rowptr[i] = r;
        g_pos[i] = r;
    }
}

// ---------------- CSR fill (4 edges/thread, batched) ------------------------
__global__ void k_fill(const void* __restrict__ ei, int E) {
    bool w64 = g_is64 != 0;
    int i = (blockIdx.x * blockDim.x + threadIdx.x) * 4;
    if (i >= E) return;
    int n = min(4, E - i);
    int s[4], d[4], pos[4];
    #pragma unroll
    for (int q = 0; q < 4; q++) if (q < n) {
        s[q] = ld_idx(ei, i + q, w64);
        d[q] = ld_idx(ei, (long long)E + i + q, w64);
    }
    #pragma unroll
    for (int q = 0; q < 4; q++) if (q < n) pos[q] = atomicAdd(&g_pos[d[q]], 1);
    #pragma unroll
    for (int q = 0; q < 4; q++) if (q < n) g_csr[pos[q]] = s[q];
}

// ---------------- propagation + LayerNorm + ReLU + pooling ------------------
// 2 nodes/warp (16-lane halves), 8-node chains per half-warp (128 nodes/block).
// h1b rows are pre-scaled by dinv[src], so edges carry NO weight:
// agg[v] = dinv[v] * (sum_{s in N(v)} h1s[s] + h1s[v]) + b_conv.
// Pooled sums accumulate in registers across the chain (same graph), flushing
// via atomics only at graph boundaries; block stages 128 nodes per barrier.
__global__ __launch_bounds__(256) void k_main(const void* __restrict__ batch,
                                              const float* __restrict__ b_conv,
                                              const float* __restrict__ gamma,
                                              const float* __restrict__ beta,
                                              int N) {
    const bool w64 = g_is64 != 0;
    int warp = threadIdx.x >> 5, lane = threadIdx.x & 31;
    int half = lane >> 4, hl = lane & 15;
    int slot = warp * 2 + half;              // 0..15
    int vbase = blockIdx.x * 128 + slot * 8;
    __shared__ int   sgph[16];
    __shared__ float sstage[16][HDIM];
    __shared__ int   s_lo, s_hi;

    const char* h1base = (const char*)g_h1b;
    float partial[8];
    #pragma unroll
    for (int t = 0; t < 8; t++) partial[t] = 0.f;
    int cur_g = -1;

    // preload per-lane LN params (features hl*8 .. hl*8+7)
    float4 bc0 = *(const float4*)&b_conv[hl * 8];
    float4 bc1 = *(const float4*)&b_conv[hl * 8 + 4];
    float4 ga0 = *(const float4*)&gamma[hl * 8];
    float4 ga1 = *(const float4*)&gamma[hl * 8 + 4];
    float4 be0 = *(const float4*)&beta[hl * 8];
    float4 be1 = *(const float4*)&beta[hl * 8 + 4];

    for (int k = 0; k < 8; k++) {
        int v = vbase + k;
        bool val = v < N;
        float dv = 0.f; int start = 0, cnt = 0;
        if (val) { dv = g_dinv[v]; start = g_rowptr[v]; cnt = g_cnt[v]; }
        int cmax = max(cnt, __shfl_xor_sync(0xffffffffu, cnt, 16));

        float acc[8];
        {
            // self row (unweighted; zero if invalid)
            uint4 raw = val ? *(const uint4*)(h1base + ((size_t)v << 8) + hl * 16)
                            : make_uint4(0u, 0u, 0u, 0u);
            const __nv_bfloat162* p = (const __nv_bfloat162*)&raw;
            #pragma unroll
            for (int t = 0; t < 4; t++) {
                float2 f = __bfloat1622float2(p[t]);
                acc[t * 2] = f.x; acc[t * 2 + 1] = f.y;
            }
        }

        for (int base = 0; base < cmax; base += 16) {
            int e = base + hl;
            int off = -1;                          // sentinel: invalid edge
            if (e < cnt) off = g_csr[start + e] << 8;
            int m = min(16, cmax - base);
            int j = 0;
            for (; j + 4 <= m; j += 4) {
                int oqs[4]; uint4 raw[4];
                #pragma unroll
                for (int q = 0; q < 4; q++) {
                    oqs[q] = __shfl_sync(0xffffffffu, off, (half << 4) + j + q);
                    raw[q] = *(const uint4*)(h1base + max(oqs[q], 0) + hl * 16);
                }
                #pragma unroll
                for (int q = 0; q < 4; q++) {
                    if (oqs[q] >= 0) {
                        const __nv_bfloat162* p = (const __nv_bfloat162*)&raw[q];
                        #pragma unroll
                        for (int t = 0; t < 4; t++) {
                            float2 f = __bfloat1622float2(p[t]);
                            acc[t * 2] += f.x; acc[t * 2 + 1] += f.y;
                        }
                    }
                }
            }
            for (; j < m; j++) {
                int oq = __shfl_sync(0xffffffffu, off, (half << 4) + j);
                if (oq >= 0) {
                    uint4 raw = *(const uint4*)(h1base + oq + hl * 16);
                    const __nv_bfloat162* p = (const __nv_bfloat162*)&raw;
                    #pragma unroll
                    for (int t = 0; t < 4; t++) {
                        float2 f = __bfloat1622float2(p[t]);
                        acc[t * 2] += f.x; acc[t * 2 + 1] += f.y;
                    }
                }
            }
        }

        // scale + bias (dv=0 for invalid -> acc = bias, harmless)
        acc[0] = acc[0] * dv + bc0.x; acc[1] = acc[1] * dv + bc0.y;
        acc[2] = acc[2] * dv + bc0.z; acc[3] = acc[3] * dv + bc0.w;
        acc[4] = acc[4] * dv + bc1.x; acc[5] = acc[5] * dv + bc1.y;
        acc[6] = acc[6] * dv + bc1.z; acc[7] = acc[7] * dv + bc1.w;

        // LayerNorm over 128 features: 8 local + 16-lane xor tree (in-half)
        float sum = 0.f;
        #pragma unroll
        for (int t = 0; t < 8; t++) sum += acc[t];
        #pragma unroll
        for (int o = 8; o; o >>= 1) sum += __shfl_xor_sync(0xffffffffu, sum, o);
        float mu = sum * (1.f / 128.f);
        float sq = 0.f;
        #pragma unroll
        for (int t = 0; t < 8; t++) { acc[t] -= mu; sq += acc[t] * acc[t]; }
        #pragma unroll
        for (int o = 8; o; o >>= 1) sq += __shfl_xor_sync(0xffffffffu, sq, o);
        float inv = rsqrtf(sq * (1.f / 128.f) + 1e-5f);
        float y[8];
        y[0] = fmaxf(0.f, ga0.x * acc[0] * inv + be0.x);
        y[1] = fmaxf(0.f, ga0.y * acc[1] * inv + be0.y);
        y[2] = fmaxf(0.f, ga0.z * acc[2] * inv + be0.z);
        y[3] = fmaxf(0.f, ga0.w * acc[3] * inv + be0.w);
        y[4] = fmaxf(0.f, ga1.x * acc[4] * inv + be1.x);
        y[5] = fmaxf(0.f, ga1.y * acc[5] * inv + be1.y);
        y[6] = fmaxf(0.f, ga1.z * acc[6] * inv + be1.z);
        y[7] = fmaxf(0.f, ga1.w * acc[7] * inv + be1.w);

        if (val) {
            int g = ld_idx(batch, v, w64);
            if (g != cur_g) {
                if (cur_g >= 0) {   // graph boundary inside chain: flush (rare)
                    float* ro = &g_readout[(size_t)cur_g * HDIM + hl * 8];
                    #pragma unroll
                    for (int t = 0; t < 8; t++) atomicAdd(ro + t, partial[t]);
                }
                cur_g = g;
                #pragma unroll
                for (int t = 0; t < 8; t++) partial[t] = y[t];
            } else {
                #pragma unroll
                for (int t = 0; t < 8; t++) partial[t] += y[t];
            }
        }
    }

    if (hl == 0) sgph[slot] = cur_g;
    *(float4*)&sstage[slot][hl * 8]     = make_float4(partial[0], partial[1], partial[2], partial[3]);
    *(float4*)&sstage[slot][hl * 8 + 4] = make_float4(partial[4], partial[5], partial[6], partial[7]);
    __syncthreads();
    if (threadIdx.x == 0) {
        int lo = 1 << 30, hi = -1;
        for (int i = 0; i < 16; i++) {
            int gi = sgph[i];
            if (gi >= 0) { lo = min(lo, gi); hi = max(hi, gi); }
        }
        s_lo = lo; s_hi = hi;
    }
    __syncthreads();
    int lo = s_lo, hi = s_hi;
    if (hi >= 0) {
        if (hi - lo <= 3) {
            for (int g = lo; g <= hi; g++) {
                if (threadIdx.x < HDIM) {
                    float a = 0.f; bool any = false;
                    #pragma unroll
                    for (int w = 0; w < 16; w++)
                        if (sgph[w] == g) { a += sstage[w][threadIdx.x]; any = true; }
                    if (any) atomicAdd(&g_readout[(size_t)g * HDIM + threadIdx.x], a);
                }
            }
        } else {
            int g = sgph[slot];
            if (g >= 0) {
                float* ro = &g_readout[(size_t)g * HDIM + hl * 8];
                #pragma unroll
                for (int t = 0; t < 8; t++) atomicAdd(ro + t, sstage[slot][hl * 8 + t]);
            }
        }
    }
}

// ---------------- epilogue GEMM: out = readout @ W_post + b_post ------------
__global__ void k_out(const float* __restrict__ Wp, const float* __restrict__ bp,
                      float* __restrict__ out) {
    __shared__ float r[HDIM];
    int b = blockIdx.x, j = threadIdx.x;   // 64 threads
    r[j]      = g_readout[(size_t)b * HDIM + j];
    r[j + 64] = g_readout[(size_t)b * HDIM + j + 64];
    __syncthreads();
    float acc = bp[j];
    #pragma unroll 8
    for (int k = 0; k < HDIM; k++) acc += r[k] * Wp[k * CDIM + j];
    out[b * CDIM + j] = acc;
}

// ---------------- launch ----------------------------------------------------
extern "C" void kernel_launch(void* const* d_in, const int* in_sizes, int n_in,
                              void* d_out, int out_size) {
    const float* x      = (const float*)d_in[0];
    const void*  ei     = d_in[1];
    const void*  batch  = d_in[2];
    const float* W_pre  = (const float*)d_in[3];
    const float* b_pre  = (const float*)d_in[4];
    const float* W_conv = (const float*)d_in[5];
    const float* b_conv = (const float*)d_in[6];
    const float* gamma  = (const float*)d_in[7];
    const float* beta   = (const float*)d_in[8];
    const float* W_post = (const float*)d_in[9];
    const float* b_post = (const float*)d_in[10];

    int N = in_sizes[0] / FDIM;
    int E = in_sizes[1] / 2;
    int G = out_size / CDIM;
    if (N > NMAX) N = NMAX;
    if (E > EMAX) E = EMAX;
    if (G > GMAX) G = GMAX;
    int NB = (N + 1023) / 1024;
    int numTiles = (N + 63) / 64;

    cudaFuncSetAttribute(k_gemm_mma, cudaFuncAttributeMaxDynamicSharedMemorySize, GEMM_SMEM);

    {
        int ZB = (N + G * HDIM + 255) / 256;
        k_init<<<ZB + 65, 256>>>((const int*)ei, W_pre, b_pre, W_conv, N, G, ZB);
    }
    k_count<<<(E / 4 + 255) / 256, 256>>>(ei, E);
    k_scan1<<<NB, 1024>>>(N);          // produces g_dinv (gemm prescale needs it)

    if (s_fork_ok) {
        // fork after scan1: gemm (needs dinv) overlaps scan2/scan3/fill
        cudaEventRecord(s_ev1, 0);
        cudaStreamWaitEvent(s_side, s_ev1, 0);
        k_gemm_mma<<<GEMM_GRID, 256, GEMM_SMEM, s_side>>>(x, N, numTiles);
        cudaEventRecord(s_ev2, s_side);

        k_scan2<<<1, 256>>>(NB);
        k_scan3<<<NB, 1024>>>(N);
        k_fill<<<(E / 4 + 255) / 256, 256>>>(ei, E);

        cudaStreamWaitEvent(0, s_ev2, 0);
    } else {
        k_scan2<<<1, 256>>>(NB);
        k_scan3<<<NB, 1024>>>(N);
        k_gemm_mma<<<GEMM_GRID, 256, GEMM_SMEM>>>(x, N, numTiles);
        k_fill<<<(E / 4 + 255) / 256, 256>>>(ei, E);
    }

    k_main<<<(N + 127) / 128, 256>>>(batch, b_conv, gamma, beta, N);
    k_out<<<G, CDIM>>>(W_post, b_post, (float*)d_out);
}

// round 17
// speedup vs baseline: 1.0118x; 1.0118x over previous
#include <cuda_runtime.h>
#include <cuda_bf16.h>
#include <stdint.h>

// Problem constants (fixed-shape problem; runtime sizes used for loop bounds)
#define NMAX 100000
#define EMAX 1600000
#define HDIM 128
#define FDIM 128
#define CDIM 64
#define GMAX 512

// ---------------- scratch (__device__ globals; no runtime allocation) ------
__device__ __nv_bfloat16 g_h1b[(size_t)NMAX * HDIM];  // 25.6 MB: dinv[v]*h1[v] rows (bf16)
__device__ float g_dinv[NMAX];
__device__ int   g_cnt[NMAX];                 // in-degree (edges only)
__device__ int   g_rowptr[NMAX];              // exclusive scan of g_cnt
__device__ int   g_pos[NMAX];                 // fill cursor (starts = rowptr)
__device__ int   g_csr[EMAX];                 // src ids grouped by dst
__device__ int   g_blocksums[256];
__device__ float g_readout[GMAX * HDIM];
__device__ float g_Wf[FDIM * HDIM];           // W_pre @ W_conv
__device__ float g_bf[HDIM];                  // b_pre @ W_conv
__device__ int   g_is64;

__device__ __forceinline__ int ld_idx(const void* p, long long i, bool w64) {
    return w64 ? (int)((const long long*)p)[i] : ((const int*)p)[i];
}

// ---------------- init: zero scratch + dtype detect + fuse W_pre@W_conv -----
__global__ void k_init(const int* __restrict__ ei_words,
                       const float* __restrict__ Wpre, const float* __restrict__ bpre,
                       const float* __restrict__ Wconv, int N, int G, int ZB) {
    if ((int)blockIdx.x < ZB) {
        int i = blockIdx.x * 256 + threadIdx.x;
        if (i == 0) {
            int acc = 0;
            for (int j = 1; j < 256; j += 2) acc |= ei_words[j];
            g_is64 = (acc == 0) ? 1 : 0;
        }
        int total = N + G * HDIM;
        if (i >= total) return;
        if (i < N) g_cnt[i] = 0;
        else       g_readout[i - N] = 0.f;
    } else {
        int bi = blockIdx.x - ZB;                   // 0..64
        int i = bi * 2 + (threadIdx.x >> 7);        // row 0..129
        int j = threadIdx.x & 127;
        if (i < FDIM) {
            float a = 0.f;
            #pragma unroll 8
            for (int k = 0; k < HDIM; k++) a += Wpre[i * HDIM + k] * Wconv[k * HDIM + j];
            g_Wf[i * HDIM + j] = a;
        } else if (i == FDIM) {
            float a = 0.f;
            #pragma unroll 8
            for (int k = 0; k < HDIM; k++) a += bpre[k] * Wconv[k * HDIM + j];
            g_bf[j] = a;
        }
    }
}

// ---------------- main GEMM: h1s = dinv*(x @ Wf + bf)  (tf32 mma, persistent)
#define XS_LD 132
#define WS_LD 136
#define GEMM_SMEM ((128 * WS_LD + 128 + 64 * XS_LD) * 4)
#define GEMM_GRID 296

__device__ __forceinline__ uint32_t f2tf32(float f) {
    uint32_t o;
    asm("cvt.rna.tf32.f32 %0, %1;" : "=r"(o) : "f"(f));
    return o;
}

__global__ __launch_bounds__(256) void k_gemm_mma(const float* __restrict__ x,
                                                  int N, int numTiles) {
    extern __shared__ float smf[];
    float* ws  = smf;                        // [128][WS_LD]
    float* bfs = smf + 128 * WS_LD;          // [128]
    float* xs  = smf + 128 * WS_LD + 128;    // [64][XS_LD]

    int tid  = threadIdx.x;
    int warp = tid >> 5, lane = tid & 31;
    int g4 = lane >> 2, t4 = lane & 3;
    int wm = warp >> 2, wn = warp & 3;

    #pragma unroll
    for (int i = 0; i < 16; i++) {
        int lin = tid + i * 256;
        int r = lin >> 5, c = (lin & 31) * 4;
        float4 v = *(const float4*)&g_Wf[r * HDIM + c];
        uint32_t* dst = (uint32_t*)&ws[r * WS_LD + c];
        dst[0] = f2tf32(v.x); dst[1] = f2tf32(v.y);
        dst[2] = f2tf32(v.z); dst[3] = f2tf32(v.w);
    }
    if (tid < HDIM) bfs[tid] = g_bf[tid];

    for (int tile = blockIdx.x; tile < numTiles; tile += gridDim.x) {
        int rb = tile * 64;
        __syncthreads();
        #pragma unroll
        for (int i = 0; i < 8; i++) {
            int lin = tid + i * 256;
            int r = lin >> 5, c = (lin & 31) * 4;
            int grow = rb + r;
            float4 v = (grow < N) ? *(const float4*)&x[(size_t)grow * FDIM + c]
                                  : make_float4(0.f, 0.f, 0.f, 0.f);
            uint32_t* dst = (uint32_t*)&xs[r * XS_LD + c];
            dst[0] = f2tf32(v.x); dst[1] = f2tf32(v.y);
            dst[2] = f2tf32(v.z); dst[3] = f2tf32(v.w);
        }
        __syncthreads();

        float acc[2][4][4];
        #pragma unroll
        for (int mt = 0; mt < 2; mt++)
            #pragma unroll
            for (int nt = 0; nt < 4; nt++)
                #pragma unroll
                for (int q = 0; q < 4; q++) acc[mt][nt][q] = 0.f;

        #pragma unroll
        for (int ks = 0; ks < 16; ks++) {
            int k0 = ks * 8;
            uint32_t a[2][4];
            #pragma unroll
            for (int mt = 0; mt < 2; mt++) {
                int r0 = wm * 32 + mt * 16;
                a[mt][0] = __float_as_uint(xs[(r0 + g4    ) * XS_LD + k0 + t4    ]);
                a[mt][1] = __float_as_uint(xs[(r0 + g4 + 8) * XS_LD + k0 + t4    ]);
                a[mt][2] = __float_as_uint(xs[(r0 + g4    ) * XS_LD + k0 + t4 + 4]);
                a[mt][3] = __float_as_uint(xs[(r0 + g4 + 8) * XS_LD + k0 + t4 + 4]);
            }
            #pragma unroll
            for (int nt = 0; nt < 4; nt++) {
                int nb = wn * 32 + nt * 8 + g4;
                uint32_t b0 = __float_as_uint(ws[(k0 + t4    ) * WS_LD + nb]);
                uint32_t b1 = __float_as_uint(ws[(k0 + t4 + 4) * WS_LD + nb]);
                #pragma unroll
                for (int mt = 0; mt < 2; mt++) {
                    asm volatile(
                        "mma.sync.aligned.m16n8k8.row.col.f32.tf32.tf32.f32 "
                        "{%0,%1,%2,%3}, {%4,%5,%6,%7}, {%8,%9}, {%0,%1,%2,%3};"
                        : "+f"(acc[mt][nt][0]), "+f"(acc[mt][nt][1]),
                          "+f"(acc[mt][nt][2]), "+f"(acc[mt][nt][3])
                        : "r"(a[mt][0]), "r"(a[mt][1]), "r"(a[mt][2]), "r"(a[mt][3]),
                          "r"(b0), "r"(b1));
                }
            }
        }

        // epilogue: (acc + bias) * dinv[row], convert to bf16, store
        #pragma unroll
        for (int mt = 0; mt < 2; mt++) {
            int r0 = rb + wm * 32 + mt * 16 + g4;
            float dv0 = (r0     < N) ? g_dinv[r0]     : 0.f;
            float dv1 = (r0 + 8 < N) ? g_dinv[r0 + 8] : 0.f;
            #pragma unroll
            for (int nt = 0; nt < 4; nt++) {
                int col = wn * 32 + nt * 8 + t4 * 2;
                float bv0 = bfs[col], bv1 = bfs[col + 1];
                if (r0 < N) {
                    __nv_bfloat162 o = __float22bfloat162_rn(
                        make_float2((acc[mt][nt][0] + bv0) * dv0,
                                    (acc[mt][nt][1] + bv1) * dv0));
                    *(__nv_bfloat162*)&g_h1b[(size_t)r0 * HDIM + col] = o;
                }
                if (r0 + 8 < N) {
                    __nv_bfloat162 o = __float22bfloat162_rn(
                        make_float2((acc[mt][nt][2] + bv0) * dv1,
                                    (acc[mt][nt][3] + bv1) * dv1));
                    *(__nv_bfloat162*)&g_h1b[(size_t)(r0 + 8) * HDIM + col] = o;
                }
            }
        }
    }
}

// ---------------- degree count (4 edges/thread, batched atomics) ------------
__global__ void k_count(const void* __restrict__ ei, int E) {
    bool w64 = g_is64 != 0;
    int i = (blockIdx.x * blockDim.x + threadIdx.x) * 4;
    if (i >= E) return;
    int n = min(4, E - i);
    int d[4];
    #pragma unroll
    for (int q = 0; q < 4; q++) if (q < n) d[q] = ld_idx(ei, (long long)E + i + q, w64);
    #pragma unroll
    for (int q = 0; q < 4; q++) if (q < n) atomicAdd(&g_cnt[d[q]], 1);
}

// ---------------- exclusive scan of g_cnt -> g_rowptr (+ dinv fused) -------
__global__ void k_scan1(int N) {
    __shared__ int sm[1024];
    int i = blockIdx.x * 1024 + threadIdx.x;
    int v = (i < N) ? g_cnt[i] : 0;
    if (i < N) g_dinv[i] = rsqrtf((float)(v + 1));
    sm[threadIdx.x] = v;
    __syncthreads();
    for (int off = 1; off < 1024; off <<= 1) {
        int t = (threadIdx.x >= off) ? sm[threadIdx.x - off] : 0;
        __syncthreads();
        sm[threadIdx.x] += t;
        __syncthreads();
    }
    if (i < N) g_rowptr[i] = sm[threadIdx.x] - v;
    if (threadIdx.x == 1023) g_blocksums[blockIdx.x] = sm[1023];
}

__global__ void k_scan2(int NB) {
    __shared__ int sm[256];
    int t = threadIdx.x;
    int v = (t < NB) ? g_blocksums[t] : 0;
    sm[t] = v;
    __syncthreads();
    for (int off = 1; off < 256; off <<= 1) {
        int u = (t >= off) ? sm[t - off] : 0;
        __syncthreads();
        sm[t] += u;
        __syncthreads();
    }
    if (t < NB) g_blocksums[t] = sm[t] - v;
}

__global__ void k_scan3(int N) {
    int i = blockIdx.x * 1024 + threadIdx.x;
    if (i < N) {
        int r = g_rowptr[i] + g_blocksums[blockIdx.x];
        g_rowptr[i] = r;
        g_pos[i] = r;
    }
}

// ---------------- CSR fill (4 edges/thread, batched) ------------------------
__global__ void k_fill(const void* __restrict__ ei, int E) {
    bool w64 = g_is64 != 0;
    int i = (blockIdx.x * blockDim.x + threadIdx.x) * 4;
    if (i >= E) return;
    int n = min(4, E - i);
    int s[4], d[4], pos[4];
    #pragma unroll
    for (int q = 0; q < 4; q++) if (q < n) {
        s[q] = ld_idx(ei, i + q, w64);
        d[q] = ld_idx(ei, (long long)E + i + q, w64);
    }
    #pragma unroll
    for (int q = 0; q < 4; q++) if (q < n) pos[q] = atomicAdd(&g_pos[d[q]], 1);
    #pragma unroll
    for (int q = 0; q < 4; q++) if (q < n) g_csr[pos[q]] = s[q];
}

// ---------------- propagation + LayerNorm + ReLU + pooling ------------------
// 2 nodes/warp (16-lane halves), 8-node chains per half-warp (128 nodes/block).
// h1b rows are pre-scaled by dinv[src], so edges carry NO weight:
// agg[v] = dinv[v] * (sum_{s in N(v)} h1s[s] + h1s[v]) + b_conv.
// Pooled sums accumulate in registers across the chain (same graph), flushing
// via atomics only at graph boundaries; block stages 128 nodes per barrier.
__global__ __launch_bounds__(256) void k_main(const void* __restrict__ batch,
                                              const float* __restrict__ b_conv,
                                              const float* __restrict__ gamma,
                                              const float* __restrict__ beta,
                                              int N) {
    const bool w64 = g_is64 != 0;
    int warp = threadIdx.x >> 5, lane = threadIdx.x & 31;
    int half = lane >> 4, hl = lane & 15;
    int slot = warp * 2 + half;              // 0..15
    int vbase = blockIdx.x * 128 + slot * 8;
    __shared__ int   sgph[16];
    __shared__ float sstage[16][HDIM];
    __shared__ int   s_lo, s_hi;

    const char* h1base = (const char*)g_h1b;
    float partial[8];
    #pragma unroll
    for (int t = 0; t < 8; t++) partial[t] = 0.f;
    int cur_g = -1;

    // preload per-lane LN params (features hl*8 .. hl*8+7)
    float4 bc0 = *(const float4*)&b_conv[hl * 8];
    float4 bc1 = *(const float4*)&b_conv[hl * 8 + 4];
    float4 ga0 = *(const float4*)&gamma[hl * 8];
    float4 ga1 = *(const float4*)&gamma[hl * 8 + 4];
    float4 be0 = *(const float4*)&beta[hl * 8];
    float4 be1 = *(const float4*)&beta[hl * 8 + 4];

    for (int k = 0; k < 8; k++) {
        int v = vbase + k;
        bool val = v < N;
        float dv = 0.f; int start = 0, cnt = 0;
        if (val) { dv = g_dinv[v]; start = g_rowptr[v]; cnt = g_cnt[v]; }
        int cmax = max(cnt, __shfl_xor_sync(0xffffffffu, cnt, 16));

        float acc[8];
        {
            // self row (unweighted; zero if invalid)
            uint4 raw = val ? *(const uint4*)(h1base + ((size_t)v << 8) + hl * 16)
                            : make_uint4(0u, 0u, 0u, 0u);
            const __nv_bfloat162* p = (const __nv_bfloat162*)&raw;
            #pragma unroll
            for (int t = 0; t < 4; t++) {
                float2 f = __bfloat1622float2(p[t]);
                acc[t * 2] = f.x; acc[t * 2 + 1] = f.y;
            }
        }

        for (int base = 0; base < cmax; base += 16) {
            int e = base + hl;
            int off = -1;                          // sentinel: invalid edge
            if (e < cnt) off = g_csr[start + e] << 8;
            int m = min(16, cmax - base);
            int j = 0;
            for (; j + 4 <= m; j += 4) {
                int oqs[4]; uint4 raw[4];
                #pragma unroll
                for (int q = 0; q < 4; q++) {
                    oqs[q] = __shfl_sync(0xffffffffu, off, (half << 4) + j + q);
                    raw[q] = *(const uint4*)(h1base + max(oqs[q], 0) + hl * 16);
                }
                #pragma unroll
                for (int q = 0; q < 4; q++) {
                    if (oqs[q] >= 0) {
                        const __nv_bfloat162* p = (const __nv_bfloat162*)&raw[q];
                        #pragma unroll
                        for (int t = 0; t < 4; t++) {
                            float2 f = __bfloat1622float2(p[t]);
                            acc[t * 2] += f.x; acc[t * 2 + 1] += f.y;
                        }
                    }
                }
            }
            for (; j < m; j++) {
                int oq = __shfl_sync(0xffffffffu, off, (half << 4) + j);
                if (oq >= 0) {
                    uint4 raw = *(const uint4*)(h1base + oq + hl * 16);
                    const __nv_bfloat162* p = (const __nv_bfloat162*)&raw;
                    #pragma unroll
                    for (int t = 0; t < 4; t++) {
                        float2 f = __bfloat1622float2(p[t]);
                        acc[t * 2] += f.x; acc[t * 2 + 1] += f.y;
                    }
                }
            }
        }

        // scale + bias (dv=0 for invalid -> acc = bias, harmless)
        acc[0] = acc[0] * dv + bc0.x; acc[1] = acc[1] * dv + bc0.y;
        acc[2] = acc[2] * dv + bc0.z; acc[3] = acc[3] * dv + bc0.w;
        acc[4] = acc[4] * dv + bc1.x; acc[5] = acc[5] * dv + bc1.y;
        acc[6] = acc[6] * dv + bc1.z; acc[7] = acc[7] * dv + bc1.w;

        // LayerNorm over 128 features: 8 local + 16-lane xor tree (in-half)
        float sum = 0.f;
        #pragma unroll
        for (int t = 0; t < 8; t++) sum += acc[t];
        #pragma unroll
        for (int o = 8; o; o >>= 1) sum += __shfl_xor_sync(0xffffffffu, sum, o);
        float mu = sum * (1.f / 128.f);
        float sq = 0.f;
        #pragma unroll
        for (int t = 0; t < 8; t++) { acc[t] -= mu; sq += acc[t] * acc[t]; }
        #pragma unroll
        for (int o = 8; o; o >>= 1) sq += __shfl_xor_sync(0xffffffffu, sq, o);
        float inv = rsqrtf(sq * (1.f / 128.f) + 1e-5f);
        float y[8];
        y[0] = fmaxf(0.f, ga0.x * acc[0] * inv + be0.x);
        y[1] = fmaxf(0.f, ga0.y * acc[1] * inv + be0.y);
        y[2] = fmaxf(0.f, ga0.z * acc[2] * inv + be0.z);
        y[3] = fmaxf(0.f, ga0.w * acc[3] * inv + be0.w);
        y[4] = fmaxf(0.f, ga1.x * acc[4] * inv + be1.x);
        y[5] = fmaxf(0.f, ga1.y * acc[5] * inv + be1.y);
        y[6] = fmaxf(0.f, ga1.z * acc[6] * inv + be1.z);
        y[7] = fmaxf(0.f, ga1.w * acc[7] * inv + be1.w);

        if (val) {
            int g = ld_idx(batch, v, w64);
            if (g != cur_g) {
                if (cur_g >= 0) {   // graph boundary inside chain: flush (rare)
                    float* ro = &g_readout[(size_t)cur_g * HDIM + hl * 8];
                    #pragma unroll
                    for (int t = 0; t < 8; t++) atomicAdd(ro + t, partial[t]);
                }
                cur_g = g;
                #pragma unroll
                for (int t = 0; t < 8; t++) partial[t] = y[t];
            } else {
                #pragma unroll
                for (int t = 0; t < 8; t++) partial[t] += y[t];
            }
        }
    }

    if (hl == 0) sgph[slot] = cur_g;
    *(float4*)&sstage[slot][hl * 8]     = make_float4(partial[0], partial[1], partial[2], partial[3]);
    *(float4*)&sstage[slot][hl * 8 + 4] = make_float4(partial[4], partial[5], partial[6], partial[7]);
    __syncthreads();
    if (threadIdx.x == 0) {
        int lo = 1 << 30, hi = -1;
        for (int i = 0; i < 16; i++) {
            int gi = sgph[i];
            if (gi >= 0) { lo = min(lo, gi); hi = max(hi, gi); }
        }
        s_lo = lo; s_hi = hi;
    }
    __syncthreads();
    int lo = s_lo, hi = s_hi;
    if (hi >= 0) {
        if (hi - lo <= 3) {
            for (int g = lo; g <= hi; g++) {
                if (threadIdx.x < HDIM) {
                    float a = 0.f; bool any = false;
                    #pragma unroll
                    for (int w = 0; w < 16; w++)
                        if (sgph[w] == g) { a += sstage[w][threadIdx.x]; any = true; }
                    if (any) atomicAdd(&g_readout[(size_t)g * HDIM + threadIdx.x], a);
                }
            }
        } else {
            int g = sgph[slot];
            if (g >= 0) {
                float* ro = &g_readout[(size_t)g * HDIM + hl * 8];
                #pragma unroll
                for (int t = 0; t < 8; t++) atomicAdd(ro + t, sstage[slot][hl * 8 + t]);
            }
        }
    }
}

// ---------------- epilogue GEMM: out = readout @ W_post + b_post ------------
__global__ void k_out(const float* __restrict__ Wp, const float* __restrict__ bp,
                      float* __restrict__ out) {
    __shared__ float r[HDIM];
    int b = blockIdx.x, j = threadIdx.x;   // 64 threads
    r[j]      = g_readout[(size_t)b * HDIM + j];
    r[j + 64] = g_readout[(size_t)b * HDIM + j + 64];
    __syncthreads();
    float acc = bp[j];
    #pragma unroll 8
    for (int k = 0; k < HDIM; k++) acc += r[k] * Wp[k * CDIM + j];
    out[b * CDIM + j] = acc;
}

// ---------------- launch (serial, single stream — fork removed for bisection)
extern "C" void kernel_launch(void* const* d_in, const int* in_sizes, int n_in,
                              void* d_out, int out_size) {
    const float* x      = (const float*)d_in[0];
    const void*  ei     = d_in[1];
    const void*  batch  = d_in[2];
    const float* W_pre  = (const float*)d_in[3];
    const float* b_pre  = (const float*)d_in[4];
    const float* W_conv = (const float*)d_in[5];
    const float* b_conv = (const float*)d_in[6];
    const float* gamma  = (const float*)d_in[7];
    const float* beta   = (const float*)d_in[8];
    const float* W_post = (const float*)d_in[9];
    const float* b_post = (const float*)d_in[10];

    int N = in_sizes[0] / FDIM;
    int E = in_sizes[1] / 2;
    int G = out_size / CDIM;
    if (N > NMAX) N = NMAX;
    if (E > EMAX) E = EMAX;
    if (G > GMAX) G = GMAX;
    int NB = (N + 1023) / 1024;
    int numTiles = (N + 63) / 64;

    cudaFuncSetAttribute(k_gemm_mma, cudaFuncAttributeMaxDynamicSharedMemorySize, GEMM_SMEM);

    {
        int ZB = (N + G * HDIM + 255) / 256;
        k_init<<<ZB + 65, 256>>>((const int*)ei, W_pre, b_pre, W_conv, N, G, ZB);
    }
    k_count<<<(E / 4 + 255) / 256, 256>>>(ei, E);
    k_scan1<<<NB, 1024>>>(N);          // produces g_dinv (gemm prescale needs it)
    k_gemm_mma<<<GEMM_GRID, 256, GEMM_SMEM>>>(x, N, numTiles);
    k_scan2<<<1, 256>>>(NB);
    k_scan3<<<NB, 1024>>>(N);
    k_fill<<<(E / 4 + 255) / 256, 256>>>(ei, E);
    k_main<<<(N + 127) / 128, 256>>>(batch, b_conv, gamma, beta, N);
    k_out<<<G, CDIM>>>(W_post, b_post, (float*)d_out);
}